// round 4
// baseline (speedup 1.0000x reference)
#include <cuda_runtime.h>

// GradientAwareAreaUtil: per-image  sum(Y) - 0.1*(sum|vdiff| + sum|hdiff|)
// B=512 images, H=W=256, fp32. Pure HBM-streaming reduction.

#define H 256
#define W 256
#define BATCH 512
#define PENALTY 0.1f

// 256 threads = 8 warps per CTA. Warp w owns rows [32w, 32w+32).
// Lane l owns columns [8l, 8l+8) as two float4 loads (row = 64 float4).
__global__ void __launch_bounds__(256, 4)
grad_area_kernel(const float* __restrict__ Y, float* __restrict__ out)
{
    const int b    = blockIdx.x;
    const int warp = threadIdx.x >> 5;
    const int lane = threadIdx.x & 31;

    const float4* img = (const float4*)(Y + (size_t)b * (H * W));
    const int r0 = warp * 32;
    // pointer to this lane's pair of float4 in row r0
    const float4* p = img + (size_t)r0 * (W / 4) + 2 * lane;

    float area = 0.0f;
    float grad = 0.0f;

    // current row registers
    float4 a = p[0];
    float4 c = p[1];
    const float4* pn = p + (W / 4);   // next row

    #pragma unroll 4
    for (int r = r0; r < r0 + 32; ++r) {
        const bool has_next = (r + 1 < H);   // false only for warp 7, last iter
        float4 na, nc;
        if (has_next) {                       // issue next-row loads early
            na = pn[0];
            nc = pn[1];
        }

        // --- area ---
        area += (a.x + a.y) + (a.z + a.w) + (c.x + c.y) + (c.z + c.w);

        // --- horizontal diffs: 7 internal + 1 cross-lane ---
        grad += fabsf(a.x - a.y) + fabsf(a.y - a.z) + fabsf(a.z - a.w)
              + fabsf(a.w - c.x)
              + fabsf(c.x - c.y) + fabsf(c.y - c.z) + fabsf(c.z - c.w);
        float neighbor_first = __shfl_down_sync(0xffffffffu, a.x, 1);
        if (lane < 31)
            grad += fabsf(c.w - neighbor_first);

        // --- vertical diffs vs next row ---
        if (has_next) {
            grad += fabsf(a.x - na.x) + fabsf(a.y - na.y)
                  + fabsf(a.z - na.z) + fabsf(a.w - na.w)
                  + fabsf(c.x - nc.x) + fabsf(c.y - nc.y)
                  + fabsf(c.z - nc.z) + fabsf(c.w - nc.w);
            a = na;
            c = nc;
            pn += (W / 4);
        }
    }

    // --- warp reduction ---
    #pragma unroll
    for (int off = 16; off > 0; off >>= 1) {
        area += __shfl_xor_sync(0xffffffffu, area, off);
        grad += __shfl_xor_sync(0xffffffffu, grad, off);
    }

    __shared__ float s_area[8];
    __shared__ float s_grad[8];
    if (lane == 0) {
        s_area[warp] = area;
        s_grad[warp] = grad;
    }
    __syncthreads();

    if (threadIdx.x == 0) {
        float ta = 0.0f, tg = 0.0f;
        #pragma unroll
        for (int i = 0; i < 8; ++i) {
            ta += s_area[i];
            tg += s_grad[i];
        }
        out[b] = ta - PENALTY * tg;
    }
}

extern "C" void kernel_launch(void* const* d_in, const int* in_sizes, int n_in,
                              void* d_out, int out_size)
{
    const float* Y  = (const float*)d_in[0];
    float*       out = (float*)d_out;
    grad_area_kernel<<<BATCH, 256>>>(Y, out);
}

// round 7
// speedup vs baseline: 1.0360x; 1.0360x over previous
#include <cuda_runtime.h>

// GradientAwareAreaUtil: per-image  sum(Y) - 0.1*(sum|vdiff| + sum|hdiff|)
// B=512 images, H=W=256, fp32. HBM-streaming reduction.
//
// Layout: grid = 1024 CTAs, CTA c handles image c>>1, row half (c&1)*128.
// 128 threads = 4 warps; warp w owns a 32-row band. Lane l owns cols [8l,8l+8)
// as two float4 loads. 4-deep register row-ring gives every load >=2 full
// iterations before first use -> ~5 LDG.128 in flight per warp.

#define H 256
#define W 256
#define BATCH 512
#define PENALTY 0.1f
#define R4 (W / 4)          // 64 float4 per row

__device__ __forceinline__ void step_row(
    const float4& Cx, const float4& Cy,     // current row (8 floats)
    const float4& Nx, const float4& Ny,     // next row
    int lane, bool do_vdiff,
    float& area, float& grad)
{
    area += ((Cx.x + Cx.y) + (Cx.z + Cx.w)) + ((Cy.x + Cy.y) + (Cy.z + Cy.w));

    // horizontal: 7 internal diffs + 1 cross-lane
    grad += fabsf(Cx.x - Cx.y) + fabsf(Cx.y - Cx.z) + fabsf(Cx.z - Cx.w)
          + fabsf(Cx.w - Cy.x)
          + fabsf(Cy.x - Cy.y) + fabsf(Cy.y - Cy.z) + fabsf(Cy.z - Cy.w);
    float nf = __shfl_down_sync(0xffffffffu, Cx.x, 1);
    if (lane < 31)
        grad += fabsf(Cy.w - nf);

    if (do_vdiff) {
        grad += fabsf(Cx.x - Nx.x) + fabsf(Cx.y - Nx.y)
              + fabsf(Cx.z - Nx.z) + fabsf(Cx.w - Nx.w)
              + fabsf(Cy.x - Ny.x) + fabsf(Cy.y - Ny.y)
              + fabsf(Cy.z - Ny.z) + fabsf(Cy.w - Ny.w);
    }
}

__global__ void __launch_bounds__(128, 7)
grad_area_kernel(const float* __restrict__ Y, float* __restrict__ out)
{
    const int cta  = blockIdx.x;          // 0..1023
    const int b    = cta >> 1;            // image
    const int half = cta & 1;             // row half
    const int warp = threadIdx.x >> 5;
    const int lane = threadIdx.x & 31;

    const int r0 = half * 128 + warp * 32;            // band start row
    const bool last_band = (r0 == H - 32);            // r0 == 224

    const float4* p = (const float4*)Y
                    + (size_t)b * (H * R4) + (size_t)r0 * R4 + 2 * lane;

    // 4-deep row ring: a0..a3, each holds one row's 8 floats for this lane
    float4 a0x = p[0];        float4 a0y = p[1];          // row r0
    float4 a1x = p[R4];       float4 a1y = p[R4 + 1];     // row r0+1
    float4 a2x = p[2 * R4];   float4 a2y = p[2 * R4 + 1]; // row r0+2
    float4 a3x, a3y;
    p += 3 * R4;                                          // -> row r0+3

    float area = 0.0f, grad = 0.0f;

    // Sub-iter k computes row r0+j and loads row r0+j+3 (>=2 iters ahead of use).
    // Loads needed up to row r0+32 (overlap) -> loads at j<=29; last band stops
    // at row 255 -> skip the j==29 load there; last band skips vdiff at j==31.
    #pragma unroll
    for (int j = 0; j < 32; j += 4) {
        // k = j+0: load -> a3, cur = a0, next = a1
        if (j + 3 <= 29 + 3) {  // always true; kept for symmetry
            if (!(last_band && j + 3 > 31)) { a3x = p[0]; a3y = p[1]; p += R4; }
        }
        step_row(a0x, a0y, a1x, a1y, lane, true, area, grad);

        // k = j+1: load -> a0, cur = a1, next = a2
        if (j + 4 <= 32) {
            if (!(last_band && j + 4 > 31)) { a0x = p[0]; a0y = p[1]; p += R4; }
        }
        step_row(a1x, a1y, a2x, a2y, lane, true, area, grad);

        // k = j+2: load -> a1, cur = a2, next = a3
        if (j + 5 <= 32) {
            if (!(last_band && j + 5 > 31)) { a1x = p[0]; a1y = p[1]; p += R4; }
        }
        step_row(a2x, a2y, a3x, a3y, lane, true, area, grad);

        // k = j+3: load -> a2, cur = a3, next = a0
        if (j + 6 <= 32) {
            if (!(last_band && j + 6 > 31)) { a2x = p[0]; a2y = p[1]; p += R4; }
        }
        step_row(a3x, a3y, a0x, a0y, lane,
                 !(last_band && j + 3 == 31), area, grad);
    }

    // warp reduction
    #pragma unroll
    for (int off = 16; off > 0; off >>= 1) {
        area += __shfl_xor_sync(0xffffffffu, area, off);
        grad += __shfl_xor_sync(0xffffffffu, grad, off);
    }

    __shared__ float s_area[4];
    __shared__ float s_grad[4];
    if (lane == 0) { s_area[warp] = area; s_grad[warp] = grad; }
    __syncthreads();

    if (threadIdx.x == 0) {
        float ta = (s_area[0] + s_area[1]) + (s_area[2] + s_area[3]);
        float tg = (s_grad[0] + s_grad[1]) + (s_grad[2] + s_grad[3]);
        atomicAdd(out + b, ta - PENALTY * tg);
    }
}

extern "C" void kernel_launch(void* const* d_in, const int* in_sizes, int n_in,
                              void* d_out, int out_size)
{
    const float* Y   = (const float*)d_in[0];
    float*       out = (float*)d_out;
    cudaMemsetAsync(out, 0, BATCH * sizeof(float), 0);
    grad_area_kernel<<<BATCH * 2, 128>>>(Y, out);
}